// round 15
// baseline (speedup 1.0000x reference)
#include <cuda_runtime.h>
#include <cuda_bf16.h>
#include <math.h>
#include <stdint.h>

#define T_LEN  16
#define C_DIM  192
#define DIN    384
#define DSTATE 16
#define DTRANK 12
#define DB_STR 48
#define HW     784
#define NTHR   384
#define UST    388
#define XNS    200
#define YST    392

// planar weight fragments: one uint per (fragment,lane) -> every load is LDG.32
__device__ uint32_t g_w1fa[12 * 96 * 2 * 32];
__device__ uint32_t g_w1fb[12 * 96 * 2 * 32];
__device__ uint32_t g_w2fa[24 * 24 * 2 * 32];
__device__ uint32_t g_w2fb[24 * 24 * 2 * 32];

__device__ __forceinline__ float siluf(float v) {
    return __fdividef(v, 1.0f + __expf(-v));
}
__device__ __forceinline__ uint32_t bfpack(float v) {
    __nv_bfloat16 h = __float2bfloat16(v);
    __nv_bfloat16 l = __float2bfloat16(v - __bfloat162float(h));
    return (uint32_t)__bfloat16_as_ushort(h) | ((uint32_t)__bfloat16_as_ushort(l) << 16);
}
__device__ __forceinline__ uint32_t pack2bf(float a, float b, int term) {
    __nv_bfloat16 ha = __float2bfloat16(a), hb = __float2bfloat16(b);
    if (term == 0)
        return (uint32_t)__bfloat16_as_ushort(ha) | ((uint32_t)__bfloat16_as_ushort(hb) << 16);
    __nv_bfloat16 la = __float2bfloat16(a - __bfloat162float(ha));
    __nv_bfloat16 lb = __float2bfloat16(b - __bfloat162float(hb));
    return (uint32_t)__bfloat16_as_ushort(la) | ((uint32_t)__bfloat16_as_ushort(lb) << 16);
}

#define MMA_BF16(d, a0, a1, a2, a3, b0, b1)                                   \
    asm volatile("mma.sync.aligned.m16n8k16.row.col.f32.bf16.bf16.f32 "       \
                 "{%0,%1,%2,%3}, {%4,%5,%6,%7}, {%8,%9}, {%0,%1,%2,%3};"      \
                 : "+f"((d)[0]), "+f"((d)[1]), "+f"((d)[2]), "+f"((d)[3])     \
                 : "r"(a0), "r"(a1), "r"(a2), "r"(a3), "r"(b0), "r"(b1))

__global__ void prep_kernel(const float* __restrict__ w1,
                            const float* __restrict__ w2) {
    int id = blockIdx.x * blockDim.x + threadIdx.x;
    if (id < 12 * 96 * 2 * 32) {
        int lane = id & 31, s = id >> 5, term = s & 1, r = s >> 1;
        int ng = r % 96, ks = r / 96;
        int c  = ng * 8 + (lane >> 2);
        int k0 = ks * 16 + 2 * (lane & 3);
        g_w1fa[id] = pack2bf(w1[k0 * 768 + c],       w1[(k0 + 1) * 768 + c], term);
        g_w1fb[id] = pack2bf(w1[(k0 + 8) * 768 + c], w1[(k0 + 9) * 768 + c], term);
    } else {
        int j = id - 12 * 96 * 2 * 32;
        int lane = j & 31, s = j >> 5, term = s & 1, r = s >> 1;
        int ng = r % 24, ks = r / 24;
        int c  = ng * 8 + (lane >> 2);
        int k0 = ks * 16 + 2 * (lane & 3);
        g_w2fa[j] = pack2bf(w2[k0 * 192 + c],       w2[(k0 + 1) * 192 + c], term);
        g_w2fb[j] = pack2bf(w2[(k0 + 8) * 192 + c], w2[(k0 + 9) * 192 + c], term);
    }
}

// smem: [0,12800) xn hi/lo -> D partials -> yhi plane (stride 392)
//       [12800,37632) u [16][388] f32
//       [37632,62464) z [16][388] f32 (y packed in place) -> ylo plane
//       [62464,65536) db [16][48]
__global__ __launch_bounds__(NTHR, 3)
void mamba_fused_kernel(const float* __restrict__ x,
                        const float* __restrict__ norm_w,
                        const float* __restrict__ conv_w,
                        const float* __restrict__ conv_b,
                        const float* __restrict__ x_proj_w,
                        const float* __restrict__ dt_proj_w,
                        const float* __restrict__ dt_proj_b,
                        const float* __restrict__ A_log,
                        const float* __restrict__ Dp,
                        float* __restrict__ out)
{
    extern __shared__ char smraw[];
    __nv_bfloat16* s_xnh = (__nv_bfloat16*)(smraw);
    __nv_bfloat16* s_xnl = (__nv_bfloat16*)(smraw + 6400);
    __nv_bfloat16* s_yhi = (__nv_bfloat16*)(smraw);
    __nv_bfloat16* s_ylo = (__nv_bfloat16*)(smraw + 37632);
    float* s_part = (float*)(smraw);
    float* s_u  = (float*)(smraw + 12800);
    float* s_z  = (float*)(smraw + 37632);
    float* s_db = (float*)(smraw + 62464);

    const int tid  = threadIdx.x;
    const int lane = tid & 31;
    const int wid  = tid >> 5;
    const int g4   = lane >> 2;
    const int m2   = (lane & 3) * 2;

    const int n  = blockIdx.x;
    const int b  = n / HW;
    const int hw = n - b * HW;
    const size_t tstride = (size_t)HW * C_DIM;
    const size_t base0   = ((size_t)b * T_LEN * HW + hw) * C_DIM;

    // ---- A: load + RMSNorm -> xn hi/lo ----
    for (int t = wid; t < T_LEN; t += 12) {
        const float* row = x + base0 + (size_t)t * tstride;
        float v[6], ss = 0.f;
        #pragma unroll
        for (int i = 0; i < 6; i++) { v[i] = row[lane + 32 * i]; ss = fmaf(v[i], v[i], ss); }
        #pragma unroll
        for (int o = 16; o; o >>= 1) ss += __shfl_xor_sync(0xffffffffu, ss, o);
        float nrm = rsqrtf(ss * (1.0f / 192.0f) + 1e-6f);
        #pragma unroll
        for (int i = 0; i < 6; i++) {
            int c = lane + 32 * i;
            float xv = v[i] * nrm * norm_w[c];
            __nv_bfloat16 h = __float2bfloat16(xv);
            s_xnh[t * XNS + c] = h;
            s_xnl[t * XNS + c] = __float2bfloat16(xv - __bfloat162float(h));
        }
    }
    __syncthreads();

    // ---- B: in_proj via bf16 MMA (planar LDG.32 weight fragments) ----
    {
        float acc[32];
        #pragma unroll
        for (int i = 0; i < 32; i++) acc[i] = 0.f;
        #pragma unroll 1
        for (int ks = 0; ks < 12; ks++) {
            int kk = ks * 16 + m2;
            uint32_t ah0 = *(const uint32_t*)(s_xnh + g4 * XNS + kk);
            uint32_t ah1 = *(const uint32_t*)(s_xnh + (g4 + 8) * XNS + kk);
            uint32_t ah2 = *(const uint32_t*)(s_xnh + g4 * XNS + kk + 8);
            uint32_t ah3 = *(const uint32_t*)(s_xnh + (g4 + 8) * XNS + kk + 8);
            uint32_t al0 = *(const uint32_t*)(s_xnl + g4 * XNS + kk);
            uint32_t al1 = *(const uint32_t*)(s_xnl + (g4 + 8) * XNS + kk);
            uint32_t al2 = *(const uint32_t*)(s_xnl + g4 * XNS + kk + 8);
            uint32_t al3 = *(const uint32_t*)(s_xnl + (g4 + 8) * XNS + kk + 8);
            #pragma unroll
            for (int ng = 0; ng < 8; ng++) {
                int gng = wid * 8 + ng;
                int ih = ((ks * 96 + gng) * 2 + 0) * 32 + lane;
                int il = ((ks * 96 + gng) * 2 + 1) * 32 + lane;
                uint32_t bhx = g_w1fa[ih], bhy = g_w1fb[ih];
                uint32_t blx = g_w1fa[il], bly = g_w1fb[il];
                MMA_BF16(acc + ng * 4, ah0, ah1, ah2, ah3, bhx, bhy);
                MMA_BF16(acc + ng * 4, al0, al1, al2, al3, bhx, bhy);
                MMA_BF16(acc + ng * 4, ah0, ah1, ah2, ah3, blx, bly);
            }
        }
        #pragma unroll
        for (int ng = 0; ng < 8; ng++) {
            int gc = wid * 64 + ng * 8 + m2;
            float d0 = acc[ng*4+0], d1 = acc[ng*4+1], d2 = acc[ng*4+2], d3 = acc[ng*4+3];
            if (gc < DIN) {
                *(float2*)(s_u + g4 * UST + gc)       = make_float2(d0, d1);
                *(float2*)(s_u + (g4 + 8) * UST + gc) = make_float2(d2, d3);
            } else {
                int zc = gc - DIN;
                *(float2*)(s_z + g4 * UST + zc)       = make_float2(siluf(d0), siluf(d1));
                *(float2*)(s_z + (g4 + 8) * UST + zc) = make_float2(siluf(d2), siluf(d3));
            }
        }
    }
    __syncthreads();

    // ---- C: depthwise conv + silu, in place over u ----
    {
        const int c = tid;
        const float4 cw = *(const float4*)(conv_w + c * 4);
        const float cb = conv_b[c];
        float um3 = 0.f, um2 = 0.f, um1 = 0.f;
        #pragma unroll
        for (int t = 0; t < T_LEN; t++) {
            float u0 = s_u[t * UST + c];
            float a = cb;
            a = fmaf(um3, cw.x, a);
            a = fmaf(um2, cw.y, a);
            a = fmaf(um1, cw.z, a);
            a = fmaf(u0,  cw.w, a);
            s_u[t * UST + c] = siluf(a);
            um3 = um2; um2 = um1; um1 = u0;
        }
    }
    __syncthreads();

    // ---- D: x_proj split-k across 12 warps ----
    {
        const int tg  = wid & 3;
        const int ksg = wid >> 2;
        if (lane < 22) {
            const float2* wrow = (const float2*)x_proj_w + lane;
            const int k0 = ksg * 128;
            const float* r0 = s_u + (tg     ) * UST;
            const float* r1 = s_u + (tg +  4) * UST;
            const float* r2 = s_u + (tg +  8) * UST;
            const float* r3 = s_u + (tg + 12) * UST;
            float a00=0.f,a01=0.f,a10=0.f,a11=0.f,a20=0.f,a21=0.f,a30=0.f,a31=0.f;
            #pragma unroll 2
            for (int k = k0; k < k0 + 128; k += 4) {
                float2 w0 = wrow[(k+0)*22], w1 = wrow[(k+1)*22];
                float2 w2 = wrow[(k+2)*22], w3 = wrow[(k+3)*22];
                float4 u0 = *(const float4*)(r0+k), u1 = *(const float4*)(r1+k);
                float4 u2 = *(const float4*)(r2+k), u3 = *(const float4*)(r3+k);
                a00=fmaf(u0.x,w0.x,a00); a01=fmaf(u0.x,w0.y,a01);
                a00=fmaf(u0.y,w1.x,a00); a01=fmaf(u0.y,w1.y,a01);
                a00=fmaf(u0.z,w2.x,a00); a01=fmaf(u0.z,w2.y,a01);
                a00=fmaf(u0.w,w3.x,a00); a01=fmaf(u0.w,w3.y,a01);
                a10=fmaf(u1.x,w0.x,a10); a11=fmaf(u1.x,w0.y,a11);
                a10=fmaf(u1.y,w1.x,a10); a11=fmaf(u1.y,w1.y,a11);
                a10=fmaf(u1.z,w2.x,a10); a11=fmaf(u1.z,w2.y,a11);
                a10=fmaf(u1.w,w3.x,a10); a11=fmaf(u1.w,w3.y,a11);
                a20=fmaf(u2.x,w0.x,a20); a21=fmaf(u2.x,w0.y,a21);
                a20=fmaf(u2.y,w1.x,a20); a21=fmaf(u2.y,w1.y,a21);
                a20=fmaf(u2.z,w2.x,a20); a21=fmaf(u2.z,w2.y,a21);
                a20=fmaf(u2.w,w3.x,a20); a21=fmaf(u2.w,w3.y,a21);
                a30=fmaf(u3.x,w0.x,a30); a31=fmaf(u3.x,w0.y,a31);
                a30=fmaf(u3.y,w1.x,a30); a31=fmaf(u3.y,w1.y,a31);
                a30=fmaf(u3.z,w2.x,a30); a31=fmaf(u3.z,w2.y,a31);
                a30=fmaf(u3.w,w3.x,a30); a31=fmaf(u3.w,w3.y,a31);
            }
            float* pp = s_part + ksg * 768;
            *(float2*)(pp + (tg     ) * DB_STR + 2*lane) = make_float2(a00,a01);
            *(float2*)(pp + (tg +  4) * DB_STR + 2*lane) = make_float2(a10,a11);
            *(float2*)(pp + (tg +  8) * DB_STR + 2*lane) = make_float2(a20,a21);
            *(float2*)(pp + (tg + 12) * DB_STR + 2*lane) = make_float2(a30,a31);
        }
    }
    __syncthreads();
    if (tid < 352) {
        int t = tid / 22, j = tid - t * 22;
        int o = t * DB_STR + 2 * j;
        float2 p0 = *(const float2*)(s_part + o);
        float2 p1 = *(const float2*)(s_part + 768 + o);
        float2 p2 = *(const float2*)(s_part + 1536 + o);
        *(float2*)(s_db + o) = make_float2(p0.x + p1.x + p2.x, p0.y + p1.y + p2.y);
    }
    __syncthreads();

    // ---- E: dt_proj + softplus -> registers ----
    float dtv[T_LEN];
    {
        const int c = tid;
        float wreg[DTRANK];
        #pragma unroll
        for (int r = 0; r < DTRANK; r++) wreg[r] = dt_proj_w[r * DIN + c];
        const float bias = dt_proj_b[c];
        #pragma unroll
        for (int t = 0; t < T_LEN; t++) {
            const float4* dr = (const float4*)(s_db + t * DB_STR);
            float4 d0 = dr[0], d1 = dr[1], d2 = dr[2];
            float a = bias;
            a=fmaf(d0.x,wreg[0],a); a=fmaf(d0.y,wreg[1],a); a=fmaf(d0.z,wreg[2],a); a=fmaf(d0.w,wreg[3],a);
            a=fmaf(d1.x,wreg[4],a); a=fmaf(d1.y,wreg[5],a); a=fmaf(d1.z,wreg[6],a); a=fmaf(d1.w,wreg[7],a);
            a=fmaf(d2.x,wreg[8],a); a=fmaf(d2.y,wreg[9],a); a=fmaf(d2.z,wreg[10],a); a=fmaf(d2.w,wreg[11],a);
            dtv[t] = (a > 20.f) ? a : log1pf(__expf(a));
        }
    }

    // ---- F: selective scan (R11-proven A[16] form); y packed over z ----
    {
        const int c = tid;
        float A[DSTATE];
        const float4* Ap = (const float4*)(A_log + c * DSTATE);
        #pragma unroll
        for (int q = 0; q < 4; q++) {
            float4 av = Ap[q];
            A[4*q+0] = -__expf(av.x); A[4*q+1] = -__expf(av.y);
            A[4*q+2] = -__expf(av.z); A[4*q+3] = -__expf(av.w);
        }
        float h[DSTATE];
        #pragma unroll
        for (int s = 0; s < DSTATE; s++) h[s] = 0.f;
        const float Dc = Dp[c];
        #pragma unroll 1
        for (int t = 0; t < T_LEN; t++) {
            float dt_t = dtv[t];
            float ucv  = s_u[t * UST + c];
            float du   = dt_t * ucv;
            const float4* B4 = (const float4*)(s_db + t * DB_STR + DTRANK);
            const float4* C4 = (const float4*)(s_db + t * DB_STR + DTRANK + DSTATE);
            float y = 0.f;
            #pragma unroll
            for (int q = 0; q < 4; q++) {
                float4 Bv = B4[q], Cv = C4[q];
                float dA, hb;
                dA=__expf(dt_t*A[4*q+0]); hb=fmaf(h[4*q+0],dA,du*Bv.x); h[4*q+0]=hb; y=fmaf(hb,Cv.x,y);
                dA=__expf(dt_t*A[4*q+1]); hb=fmaf(h[4*q+1],dA,du*Bv.y); h[4*q+1]=hb; y=fmaf(hb,Cv.y,y);
                dA=__expf(dt_t*A[4*q+2]); hb=fmaf(h[4*q+2],dA,du*Bv.z); h[4*q+2]=hb; y=fmaf(hb,Cv.z,y);
                dA=__expf(dt_t*A[4*q+3]); hb=fmaf(h[4*q+3],dA,du*Bv.w); h[4*q+3]=hb; y=fmaf(hb,Cv.w,y);
            }
            y = fmaf(ucv, Dc, y);
            float yz = y * s_z[t * UST + c];
            *(uint32_t*)(s_z + t * UST + c) = bfpack(yz);
        }
    }

    // ---- repack packed y -> yhi plane + ylo plane ----
    {
        const int c = tid;
        uint32_t yv[T_LEN];
        #pragma unroll
        for (int t = 0; t < T_LEN; t++) yv[t] = *(const uint32_t*)(s_z + t * UST + c);
        __syncthreads();
        uint16_t* ph = (uint16_t*)s_yhi;
        uint16_t* pl = (uint16_t*)s_ylo;
        #pragma unroll
        for (int t = 0; t < T_LEN; t++) {
            ph[t * YST + c] = (uint16_t)(yv[t] & 0xffff);
            pl[t * YST + c] = (uint16_t)(yv[t] >> 16);
        }
    }
    __syncthreads();

    // ---- G: out_proj via bf16 MMA + residual (planar LDG.32 fragments) ----
    {
        float acc[8];
        #pragma unroll
        for (int i = 0; i < 8; i++) acc[i] = 0.f;
        #pragma unroll 1
        for (int ks = 0; ks < 24; ks++) {
            int kk = ks * 16 + m2;
            int i00 = ((ks * 24 + wid * 2 + 0) * 2 + 0) * 32 + lane;
            int i01 = ((ks * 24 + wid * 2 + 0) * 2 + 1) * 32 + lane;
            int i10 = ((ks * 24 + wid * 2 + 1) * 2 + 0) * 32 + lane;
            int i11 = ((ks * 24 + wid * 2 + 1) * 2 + 1) * 32 + lane;
            uint32_t bh0x = g_w2fa[i00], bh0y = g_w2fb[i00];
            uint32_t bl0x = g_w2fa[i01], bl0y = g_w2fb[i01];
            uint32_t bh1x = g_w2fa[i10], bh1y = g_w2fb[i10];
            uint32_t bl1x = g_w2fa[i11], bl1y = g_w2fb[i11];
            uint32_t ah0 = *(const uint32_t*)(s_yhi + g4 * YST + kk);
            uint32_t ah1 = *(const uint32_t*)(s_yhi + (g4 + 8) * YST + kk);
            uint32_t ah2 = *(const uint32_t*)(s_yhi + g4 * YST + kk + 8);
            uint32_t ah3 = *(const uint32_t*)(s_yhi + (g4 + 8) * YST + kk + 8);
            uint32_t al0 = *(const uint32_t*)(s_ylo + g4 * YST + kk);
            uint32_t al1 = *(const uint32_t*)(s_ylo + (g4 + 8) * YST + kk);
            uint32_t al2 = *(const uint32_t*)(s_ylo + g4 * YST + kk + 8);
            uint32_t al3 = *(const uint32_t*)(s_ylo + (g4 + 8) * YST + kk + 8);
            MMA_BF16(acc + 0, ah0, ah1, ah2, ah3, bh0x, bh0y);
            MMA_BF16(acc + 0, al0, al1, al2, al3, bh0x, bh0y);
            MMA_BF16(acc + 0, ah0, ah1, ah2, ah3, bl0x, bl0y);
            MMA_BF16(acc + 4, ah0, ah1, ah2, ah3, bh1x, bh1y);
            MMA_BF16(acc + 4, al0, al1, al2, al3, bh1x, bh1y);
            MMA_BF16(acc + 4, ah0, ah1, ah2, ah3, bl1x, bl1y);
        }
        #pragma unroll
        for (int ng = 0; ng < 2; ng++) {
            int gc = (wid * 2 + ng) * 8 + m2;
            size_t ga = base0 + (size_t)g4 * tstride + gc;
            size_t gb = base0 + (size_t)(g4 + 8) * tstride + gc;
            float2 xa = *(const float2*)(x + ga);
            float2 xb = *(const float2*)(x + gb);
            *(float2*)(out + ga) = make_float2(xa.x + acc[ng*4+0], xa.y + acc[ng*4+1]);
            *(float2*)(out + gb) = make_float2(xb.x + acc[ng*4+2], xb.y + acc[ng*4+3]);
        }
    }
}

extern "C" void kernel_launch(void* const* d_in, const int* in_sizes, int n_in,
                              void* d_out, int out_size)
{
    (void)in_sizes; (void)n_in; (void)out_size;
    const float* x         = (const float*)d_in[0];
    const float* norm_w    = (const float*)d_in[1];
    const float* in_proj_w = (const float*)d_in[2];
    const float* conv_w    = (const float*)d_in[3];
    const float* conv_b    = (const float*)d_in[4];
    const float* x_proj_w  = (const float*)d_in[5];
    const float* dt_proj_w = (const float*)d_in[6];
    const float* dt_proj_b = (const float*)d_in[7];
    const float* A_log     = (const float*)d_in[8];
    const float* Dp        = (const float*)d_in[9];
    const float* out_pw    = (const float*)d_in[10];
    float* out = (float*)d_out;

    prep_kernel<<<432, 256>>>(in_proj_w, out_pw);

    const int smem_bytes = 65536;
    cudaFuncSetAttribute(mamba_fused_kernel,
                         cudaFuncAttributeMaxDynamicSharedMemorySize, smem_bytes);
    mamba_fused_kernel<<<2 * HW, NTHR, smem_bytes>>>(
        x, norm_w, conv_w, conv_b, x_proj_w,
        dt_proj_w, dt_proj_b, A_log, Dp, out);
}

// round 16
// speedup vs baseline: 1.3581x; 1.3581x over previous
#include <cuda_runtime.h>
#include <cuda_bf16.h>
#include <math.h>
#include <stdint.h>

#define T_LEN  16
#define C_DIM  192
#define DIN    384
#define DSTATE 16
#define DTRANK 12
#define DB_STR 48
#define HW     784
#define NTHR   384
#define UST    388
#define XNS    200
#define YST    392

__device__ uint2 g_w1f[12 * 96 * 2 * 32];
__device__ uint2 g_w2f[24 * 24 * 2 * 32];

__device__ __forceinline__ float siluf(float v) {
    return __fdividef(v, 1.0f + __expf(-v));
}
__device__ __forceinline__ uint32_t bfpack(float v) {
    __nv_bfloat16 h = __float2bfloat16(v);
    __nv_bfloat16 l = __float2bfloat16(v - __bfloat162float(h));
    return (uint32_t)__bfloat16_as_ushort(h) | ((uint32_t)__bfloat16_as_ushort(l) << 16);
}
__device__ __forceinline__ uint32_t pack2bf(float a, float b, int term) {
    __nv_bfloat16 ha = __float2bfloat16(a), hb = __float2bfloat16(b);
    if (term == 0)
        return (uint32_t)__bfloat16_as_ushort(ha) | ((uint32_t)__bfloat16_as_ushort(hb) << 16);
    __nv_bfloat16 la = __float2bfloat16(a - __bfloat162float(ha));
    __nv_bfloat16 lb = __float2bfloat16(b - __bfloat162float(hb));
    return (uint32_t)__bfloat16_as_ushort(la) | ((uint32_t)__bfloat16_as_ushort(lb) << 16);
}

#define MMA_BF16(d, a0, a1, a2, a3, b0, b1)                                   \
    asm volatile("mma.sync.aligned.m16n8k16.row.col.f32.bf16.bf16.f32 "       \
                 "{%0,%1,%2,%3}, {%4,%5,%6,%7}, {%8,%9}, {%0,%1,%2,%3};"      \
                 : "+f"((d)[0]), "+f"((d)[1]), "+f"((d)[2]), "+f"((d)[3])     \
                 : "r"(a0), "r"(a1), "r"(a2), "r"(a3), "r"(b0), "r"(b1))

__global__ void prep_kernel(const float* __restrict__ w1,
                            const float* __restrict__ w2) {
    int id = blockIdx.x * blockDim.x + threadIdx.x;
    if (id < 12 * 96 * 2 * 32) {
        int lane = id & 31, s = id >> 5, term = s & 1, r = s >> 1;
        int ng = r % 96, ks = r / 96;
        int c  = ng * 8 + (lane >> 2);
        int k0 = ks * 16 + 2 * (lane & 3);
        uint2 v;
        v.x = pack2bf(w1[k0 * 768 + c],       w1[(k0 + 1) * 768 + c], term);
        v.y = pack2bf(w1[(k0 + 8) * 768 + c], w1[(k0 + 9) * 768 + c], term);
        g_w1f[id] = v;
    } else {
        int j = id - 12 * 96 * 2 * 32;
        int lane = j & 31, s = j >> 5, term = s & 1, r = s >> 1;
        int ng = r % 24, ks = r / 24;
        int c  = ng * 8 + (lane >> 2);
        int k0 = ks * 16 + 2 * (lane & 3);
        uint2 v;
        v.x = pack2bf(w2[k0 * 192 + c],       w2[(k0 + 1) * 192 + c], term);
        v.y = pack2bf(w2[(k0 + 8) * 192 + c], w2[(k0 + 9) * 192 + c], term);
        g_w2f[j] = v;
    }
}

// smem: [0,12800) xn hi/lo -> D partials -> yhi plane (stride 392)
//       [12800,37632) u [16][388] f32
//       [37632,62464) z [16][388] f32 (y packed in place) -> ylo plane
//       [62464,65536) db [16][48]
__global__ __launch_bounds__(NTHR, 3)
void mamba_fused_kernel(const float* __restrict__ x,
                        const float* __restrict__ norm_w,
                        const float* __restrict__ conv_w,
                        const float* __restrict__ conv_b,
                        const float* __restrict__ x_proj_w,
                        const float* __restrict__ dt_proj_w,
                        const float* __restrict__ dt_proj_b,
                        const float* __restrict__ A_log,
                        const float* __restrict__ Dp,
                        float* __restrict__ out)
{
    extern __shared__ char smraw[];
    __nv_bfloat16* s_xnh = (__nv_bfloat16*)(smraw);
    __nv_bfloat16* s_xnl = (__nv_bfloat16*)(smraw + 6400);
    __nv_bfloat16* s_yhi = (__nv_bfloat16*)(smraw);
    __nv_bfloat16* s_ylo = (__nv_bfloat16*)(smraw + 37632);
    float* s_part = (float*)(smraw);
    float* s_u  = (float*)(smraw + 12800);
    float* s_z  = (float*)(smraw + 37632);
    float* s_db = (float*)(smraw + 62464);

    const int tid  = threadIdx.x;
    const int lane = tid & 31;
    const int wid  = tid >> 5;
    const int g4   = lane >> 2;
    const int m2   = (lane & 3) * 2;

    const int n  = blockIdx.x;
    const int b  = n / HW;
    const int hw = n - b * HW;
    const size_t tstride = (size_t)HW * C_DIM;
    const size_t base0   = ((size_t)b * T_LEN * HW + hw) * C_DIM;

    // ---- A: load + RMSNorm -> xn hi/lo ----
    for (int t = wid; t < T_LEN; t += 12) {
        const float* row = x + base0 + (size_t)t * tstride;
        float v[6], ss = 0.f;
        #pragma unroll
        for (int i = 0; i < 6; i++) { v[i] = row[lane + 32 * i]; ss = fmaf(v[i], v[i], ss); }
        #pragma unroll
        for (int o = 16; o; o >>= 1) ss += __shfl_xor_sync(0xffffffffu, ss, o);
        float nrm = rsqrtf(ss * (1.0f / 192.0f) + 1e-6f);
        #pragma unroll
        for (int i = 0; i < 6; i++) {
            int c = lane + 32 * i;
            float xv = v[i] * nrm * norm_w[c];
            __nv_bfloat16 h = __float2bfloat16(xv);
            s_xnh[t * XNS + c] = h;
            s_xnl[t * XNS + c] = __float2bfloat16(xv - __bfloat162float(h));
        }
    }
    __syncthreads();

    // ---- B: in_proj via bf16 MMA ----
    {
        float acc[32];
        #pragma unroll
        for (int i = 0; i < 32; i++) acc[i] = 0.f;
        #pragma unroll 1
        for (int ks = 0; ks < 12; ks++) {
            int kk = ks * 16 + m2;
            uint32_t ah0 = *(const uint32_t*)(s_xnh + g4 * XNS + kk);
            uint32_t ah1 = *(const uint32_t*)(s_xnh + (g4 + 8) * XNS + kk);
            uint32_t ah2 = *(const uint32_t*)(s_xnh + g4 * XNS + kk + 8);
            uint32_t ah3 = *(const uint32_t*)(s_xnh + (g4 + 8) * XNS + kk + 8);
            uint32_t al0 = *(const uint32_t*)(s_xnl + g4 * XNS + kk);
            uint32_t al1 = *(const uint32_t*)(s_xnl + (g4 + 8) * XNS + kk);
            uint32_t al2 = *(const uint32_t*)(s_xnl + g4 * XNS + kk + 8);
            uint32_t al3 = *(const uint32_t*)(s_xnl + (g4 + 8) * XNS + kk + 8);
            #pragma unroll
            for (int ng = 0; ng < 8; ng++) {
                int gng = wid * 8 + ng;
                uint2 bh = g_w1f[((ks * 96 + gng) * 2 + 0) * 32 + lane];
                uint2 bl = g_w1f[((ks * 96 + gng) * 2 + 1) * 32 + lane];
                MMA_BF16(acc + ng * 4, ah0, ah1, ah2, ah3, bh.x, bh.y);
                MMA_BF16(acc + ng * 4, al0, al1, al2, al3, bh.x, bh.y);
                MMA_BF16(acc + ng * 4, ah0, ah1, ah2, ah3, bl.x, bl.y);
            }
        }
        #pragma unroll
        for (int ng = 0; ng < 8; ng++) {
            int gc = wid * 64 + ng * 8 + m2;
            float d0 = acc[ng*4+0], d1 = acc[ng*4+1], d2 = acc[ng*4+2], d3 = acc[ng*4+3];
            if (gc < DIN) {
                *(float2*)(s_u + g4 * UST + gc)       = make_float2(d0, d1);
                *(float2*)(s_u + (g4 + 8) * UST + gc) = make_float2(d2, d3);
            } else {
                int zc = gc - DIN;
                *(float2*)(s_z + g4 * UST + zc)       = make_float2(siluf(d0), siluf(d1));
                *(float2*)(s_z + (g4 + 8) * UST + zc) = make_float2(siluf(d2), siluf(d3));
            }
        }
    }
    __syncthreads();

    // ---- C: depthwise conv + silu, in place over u ----
    {
        const int c = tid;
        const float4 cw = *(const float4*)(conv_w + c * 4);
        const float cb = conv_b[c];
        float um3 = 0.f, um2 = 0.f, um1 = 0.f;
        #pragma unroll
        for (int t = 0; t < T_LEN; t++) {
            float u0 = s_u[t * UST + c];
            float a = cb;
            a = fmaf(um3, cw.x, a);
            a = fmaf(um2, cw.y, a);
            a = fmaf(um1, cw.z, a);
            a = fmaf(u0,  cw.w, a);
            s_u[t * UST + c] = siluf(a);
            um3 = um2; um2 = um1; um1 = u0;
        }
    }
    __syncthreads();

    // ---- D: x_proj split-k across 12 warps ----
    {
        const int tg  = wid & 3;
        const int ksg = wid >> 2;
        if (lane < 22) {
            const float2* wrow = (const float2*)x_proj_w + lane;
            const int k0 = ksg * 128;
            const float* r0 = s_u + (tg     ) * UST;
            const float* r1 = s_u + (tg +  4) * UST;
            const float* r2 = s_u + (tg +  8) * UST;
            const float* r3 = s_u + (tg + 12) * UST;
            float a00=0.f,a01=0.f,a10=0.f,a11=0.f,a20=0.f,a21=0.f,a30=0.f,a31=0.f;
            #pragma unroll 2
            for (int k = k0; k < k0 + 128; k += 4) {
                float2 w0 = wrow[(k+0)*22], w1 = wrow[(k+1)*22];
                float2 w2 = wrow[(k+2)*22], w3 = wrow[(k+3)*22];
                float4 u0 = *(const float4*)(r0+k), u1 = *(const float4*)(r1+k);
                float4 u2 = *(const float4*)(r2+k), u3 = *(const float4*)(r3+k);
                a00=fmaf(u0.x,w0.x,a00); a01=fmaf(u0.x,w0.y,a01);
                a00=fmaf(u0.y,w1.x,a00); a01=fmaf(u0.y,w1.y,a01);
                a00=fmaf(u0.z,w2.x,a00); a01=fmaf(u0.z,w2.y,a01);
                a00=fmaf(u0.w,w3.x,a00); a01=fmaf(u0.w,w3.y,a01);
                a10=fmaf(u1.x,w0.x,a10); a11=fmaf(u1.x,w0.y,a11);
                a10=fmaf(u1.y,w1.x,a10); a11=fmaf(u1.y,w1.y,a11);
                a10=fmaf(u1.z,w2.x,a10); a11=fmaf(u1.z,w2.y,a11);
                a10=fmaf(u1.w,w3.x,a10); a11=fmaf(u1.w,w3.y,a11);
                a20=fmaf(u2.x,w0.x,a20); a21=fmaf(u2.x,w0.y,a21);
                a20=fmaf(u2.y,w1.x,a20); a21=fmaf(u2.y,w1.y,a21);
                a20=fmaf(u2.z,w2.x,a20); a21=fmaf(u2.z,w2.y,a21);
                a20=fmaf(u2.w,w3.x,a20); a21=fmaf(u2.w,w3.y,a21);
                a30=fmaf(u3.x,w0.x,a30); a31=fmaf(u3.x,w0.y,a31);
                a30=fmaf(u3.y,w1.x,a30); a31=fmaf(u3.y,w1.y,a31);
                a30=fmaf(u3.z,w2.x,a30); a31=fmaf(u3.z,w2.y,a31);
                a30=fmaf(u3.w,w3.x,a30); a31=fmaf(u3.w,w3.y,a31);
            }
            float* pp = s_part + ksg * 768;
            *(float2*)(pp + (tg     ) * DB_STR + 2*lane) = make_float2(a00,a01);
            *(float2*)(pp + (tg +  4) * DB_STR + 2*lane) = make_float2(a10,a11);
            *(float2*)(pp + (tg +  8) * DB_STR + 2*lane) = make_float2(a20,a21);
            *(float2*)(pp + (tg + 12) * DB_STR + 2*lane) = make_float2(a30,a31);
        }
    }
    __syncthreads();
    if (tid < 352) {
        int t = tid / 22, j = tid - t * 22;
        int o = t * DB_STR + 2 * j;
        float2 p0 = *(const float2*)(s_part + o);
        float2 p1 = *(const float2*)(s_part + 768 + o);
        float2 p2 = *(const float2*)(s_part + 1536 + o);
        *(float2*)(s_db + o) = make_float2(p0.x + p1.x + p2.x, p0.y + p1.y + p2.y);
    }
    __syncthreads();

    // ---- E: dt_proj + softplus -> registers ----
    float dtv[T_LEN];
    {
        const int c = tid;
        float wreg[DTRANK];
        #pragma unroll
        for (int r = 0; r < DTRANK; r++) wreg[r] = dt_proj_w[r * DIN + c];
        const float bias = dt_proj_b[c];
        #pragma unroll
        for (int t = 0; t < T_LEN; t++) {
            const float4* dr = (const float4*)(s_db + t * DB_STR);
            float4 d0 = dr[0], d1 = dr[1], d2 = dr[2];
            float a = bias;
            a=fmaf(d0.x,wreg[0],a); a=fmaf(d0.y,wreg[1],a); a=fmaf(d0.z,wreg[2],a); a=fmaf(d0.w,wreg[3],a);
            a=fmaf(d1.x,wreg[4],a); a=fmaf(d1.y,wreg[5],a); a=fmaf(d1.z,wreg[6],a); a=fmaf(d1.w,wreg[7],a);
            a=fmaf(d2.x,wreg[8],a); a=fmaf(d2.y,wreg[9],a); a=fmaf(d2.z,wreg[10],a); a=fmaf(d2.w,wreg[11],a);
            dtv[t] = (a > 20.f) ? a : log1pf(__expf(a));
        }
    }

    // ---- F: selective scan; packed y (hi|lo) over z in place ----
    {
        const int c = tid;
        float A[DSTATE];
        const float4* Ap = (const float4*)(A_log + c * DSTATE);
        #pragma unroll
        for (int q = 0; q < 4; q++) {
            float4 av = Ap[q];
            A[4*q+0] = -__expf(av.x); A[4*q+1] = -__expf(av.y);
            A[4*q+2] = -__expf(av.z); A[4*q+3] = -__expf(av.w);
        }
        float h[DSTATE];
        #pragma unroll
        for (int s = 0; s < DSTATE; s++) h[s] = 0.f;
        const float Dc = Dp[c];
        #pragma unroll 1
        for (int t = 0; t < T_LEN; t++) {
            float dt_t = dtv[t];
            float ucv  = s_u[t * UST + c];
            float du   = dt_t * ucv;
            const float4* B4 = (const float4*)(s_db + t * DB_STR + DTRANK);
            const float4* C4 = (const float4*)(s_db + t * DB_STR + DTRANK + DSTATE);
            float y = 0.f;
            #pragma unroll
            for (int q = 0; q < 4; q++) {
                float4 Bv = B4[q], Cv = C4[q];
                float dA, hb;
                dA=__expf(dt_t*A[4*q+0]); hb=fmaf(h[4*q+0],dA,du*Bv.x); h[4*q+0]=hb; y=fmaf(hb,Cv.x,y);
                dA=__expf(dt_t*A[4*q+1]); hb=fmaf(h[4*q+1],dA,du*Bv.y); h[4*q+1]=hb; y=fmaf(hb,Cv.y,y);
                dA=__expf(dt_t*A[4*q+2]); hb=fmaf(h[4*q+2],dA,du*Bv.z); h[4*q+2]=hb; y=fmaf(hb,Cv.z,y);
                dA=__expf(dt_t*A[4*q+3]); hb=fmaf(h[4*q+3],dA,du*Bv.w); h[4*q+3]=hb; y=fmaf(hb,Cv.w,y);
            }
            y = fmaf(ucv, Dc, y);
            float yz = y * s_z[t * UST + c];
            *(uint32_t*)(s_z + t * UST + c) = bfpack(yz);
        }
    }

    // ---- repack packed y -> yhi plane + ylo plane ----
    {
        const int c = tid;
        uint32_t yv[T_LEN];
        #pragma unroll
        for (int t = 0; t < T_LEN; t++) yv[t] = *(const uint32_t*)(s_z + t * UST + c);
        __syncthreads();
        uint16_t* ph = (uint16_t*)s_yhi;
        uint16_t* pl = (uint16_t*)s_ylo;
        #pragma unroll
        for (int t = 0; t < T_LEN; t++) {
            ph[t * YST + c] = (uint16_t)(yv[t] & 0xffff);
            pl[t * YST + c] = (uint16_t)(yv[t] >> 16);
        }
    }
    __syncthreads();

    // ---- G: out_proj via bf16 MMA + residual ----
    {
        float acc[8];
        #pragma unroll
        for (int i = 0; i < 8; i++) acc[i] = 0.f;
        #pragma unroll 1
        for (int ks = 0; ks < 24; ks++) {
            int kk = ks * 16 + m2;
            uint2 bh0 = g_w2f[((ks * 24 + wid * 2 + 0) * 2 + 0) * 32 + lane];
            uint2 bl0 = g_w2f[((ks * 24 + wid * 2 + 0) * 2 + 1) * 32 + lane];
            uint2 bh1 = g_w2f[((ks * 24 + wid * 2 + 1) * 2 + 0) * 32 + lane];
            uint2 bl1 = g_w2f[((ks * 24 + wid * 2 + 1) * 2 + 1) * 32 + lane];
            uint32_t ah0 = *(const uint32_t*)(s_yhi + g4 * YST + kk);
            uint32_t ah1 = *(const uint32_t*)(s_yhi + (g4 + 8) * YST + kk);
            uint32_t ah2 = *(const uint32_t*)(s_yhi + g4 * YST + kk + 8);
            uint32_t ah3 = *(const uint32_t*)(s_yhi + (g4 + 8) * YST + kk + 8);
            uint32_t al0 = *(const uint32_t*)(s_ylo + g4 * YST + kk);
            uint32_t al1 = *(const uint32_t*)(s_ylo + (g4 + 8) * YST + kk);
            uint32_t al2 = *(const uint32_t*)(s_ylo + g4 * YST + kk + 8);
            uint32_t al3 = *(const uint32_t*)(s_ylo + (g4 + 8) * YST + kk + 8);
            MMA_BF16(acc + 0, ah0, ah1, ah2, ah3, bh0.x, bh0.y);
            MMA_BF16(acc + 0, al0, al1, al2, al3, bh0.x, bh0.y);
            MMA_BF16(acc + 0, ah0, ah1, ah2, ah3, bl0.x, bl0.y);
            MMA_BF16(acc + 4, ah0, ah1, ah2, ah3, bh1.x, bh1.y);
            MMA_BF16(acc + 4, al0, al1, al2, al3, bh1.x, bh1.y);
            MMA_BF16(acc + 4, ah0, ah1, ah2, ah3, bl1.x, bl1.y);
        }
        #pragma unroll
        for (int ng = 0; ng < 2; ng++) {
            int gc = (wid * 2 + ng) * 8 + m2;
            size_t ga = base0 + (size_t)g4 * tstride + gc;
            size_t gb = base0 + (size_t)(g4 + 8) * tstride + gc;
            float2 xa = *(const float2*)(x + ga);
            float2 xb = *(const float2*)(x + gb);
            *(float2*)(out + ga) = make_float2(xa.x + acc[ng*4+0], xa.y + acc[ng*4+1]);
            *(float2*)(out + gb) = make_float2(xb.x + acc[ng*4+2], xb.y + acc[ng*4+3]);
        }
    }
}

extern "C" void kernel_launch(void* const* d_in, const int* in_sizes, int n_in,
                              void* d_out, int out_size)
{
    (void)in_sizes; (void)n_in; (void)out_size;
    const float* x         = (const float*)d_in[0];
    const float* norm_w    = (const float*)d_in[1];
    const float* in_proj_w = (const float*)d_in[2];
    const float* conv_w    = (const float*)d_in[3];
    const float* conv_b    = (const float*)d_in[4];
    const float* x_proj_w  = (const float*)d_in[5];
    const float* dt_proj_w = (const float*)d_in[6];
    const float* dt_proj_b = (const float*)d_in[7];
    const float* A_log     = (const float*)d_in[8];
    const float* Dp        = (const float*)d_in[9];
    const float* out_pw    = (const float*)d_in[10];
    float* out = (float*)d_out;

    prep_kernel<<<432, 256>>>(in_proj_w, out_pw);

    const int smem_bytes = 65536;
    cudaFuncSetAttribute(mamba_fused_kernel,
                         cudaFuncAttributeMaxDynamicSharedMemorySize, smem_bytes);
    mamba_fused_kernel<<<2 * HW, NTHR, smem_bytes>>>(
        x, norm_w, conv_w, conv_b, x_proj_w,
        dt_proj_w, dt_proj_b, A_log, Dp, out);
}

// round 17
// speedup vs baseline: 1.4984x; 1.1033x over previous
#include <cuda_runtime.h>
#include <cuda_bf16.h>
#include <math.h>
#include <stdint.h>

#define T_LEN  16
#define C_DIM  192
#define DIN    384
#define DSTATE 16
#define DTRANK 12
#define DB_STR 48
#define HW     784
#define NTHR   384
#define UST    388
#define XNS    200
#define YST    392
#define UCS    388   // uc hi/lo plane stride (bf16 elems)

#define NW1 (12 * 96 * 2 * 32)
#define NW2 (24 * 24 * 2 * 32)
#define NWX (24 * 6 * 2 * 32)

__device__ uint2 g_w1f[NW1];
__device__ uint2 g_w2f[NW2];
__device__ uint2 g_wxf[NWX];

__device__ __forceinline__ float siluf(float v) {
    return __fdividef(v, 1.0f + __expf(-v));
}
__device__ __forceinline__ uint32_t bfpack(float v) {
    __nv_bfloat16 h = __float2bfloat16(v);
    __nv_bfloat16 l = __float2bfloat16(v - __bfloat162float(h));
    return (uint32_t)__bfloat16_as_ushort(h) | ((uint32_t)__bfloat16_as_ushort(l) << 16);
}
__device__ __forceinline__ uint32_t pack2bf(float a, float b, int term) {
    __nv_bfloat16 ha = __float2bfloat16(a), hb = __float2bfloat16(b);
    if (term == 0)
        return (uint32_t)__bfloat16_as_ushort(ha) | ((uint32_t)__bfloat16_as_ushort(hb) << 16);
    __nv_bfloat16 la = __float2bfloat16(a - __bfloat162float(ha));
    __nv_bfloat16 lb = __float2bfloat16(b - __bfloat162float(hb));
    return (uint32_t)__bfloat16_as_ushort(la) | ((uint32_t)__bfloat16_as_ushort(lb) << 16);
}

#define MMA_BF16(d, a0, a1, a2, a3, b0, b1)                                   \
    asm volatile("mma.sync.aligned.m16n8k16.row.col.f32.bf16.bf16.f32 "       \
                 "{%0,%1,%2,%3}, {%4,%5,%6,%7}, {%8,%9}, {%0,%1,%2,%3};"      \
                 : "+f"((d)[0]), "+f"((d)[1]), "+f"((d)[2]), "+f"((d)[3])     \
                 : "r"(a0), "r"(a1), "r"(a2), "r"(a3), "r"(b0), "r"(b1))

__global__ void prep_kernel(const float* __restrict__ w1,
                            const float* __restrict__ w2,
                            const float* __restrict__ wx) {
    int id = blockIdx.x * blockDim.x + threadIdx.x;
    if (id < NW1) {
        int lane = id & 31, s = id >> 5, term = s & 1, r = s >> 1;
        int ng = r % 96, ks = r / 96;
        int c  = ng * 8 + (lane >> 2);
        int k0 = ks * 16 + 2 * (lane & 3);
        uint2 v;
        v.x = pack2bf(w1[k0 * 768 + c],       w1[(k0 + 1) * 768 + c], term);
        v.y = pack2bf(w1[(k0 + 8) * 768 + c], w1[(k0 + 9) * 768 + c], term);
        g_w1f[id] = v;
    } else if (id < NW1 + NW2) {
        int j = id - NW1;
        int lane = j & 31, s = j >> 5, term = s & 1, r = s >> 1;
        int ng = r % 24, ks = r / 24;
        int c  = ng * 8 + (lane >> 2);
        int k0 = ks * 16 + 2 * (lane & 3);
        uint2 v;
        v.x = pack2bf(w2[k0 * 192 + c],       w2[(k0 + 1) * 192 + c], term);
        v.y = pack2bf(w2[(k0 + 8) * 192 + c], w2[(k0 + 9) * 192 + c], term);
        g_w2f[j] = v;
    } else if (id < NW1 + NW2 + NWX) {
        int j = id - NW1 - NW2;
        int lane = j & 31, s = j >> 5, term = s & 1, r = s >> 1;
        int ng = r % 6, ks = r / 6;
        int c  = ng * 8 + (lane >> 2);
        int k0 = ks * 16 + 2 * (lane & 3);
        float a0 = (c < 44) ? wx[(k0    ) * 44 + c] : 0.f;
        float a1 = (c < 44) ? wx[(k0 + 1) * 44 + c] : 0.f;
        float b0 = (c < 44) ? wx[(k0 + 8) * 44 + c] : 0.f;
        float b1 = (c < 44) ? wx[(k0 + 9) * 44 + c] : 0.f;
        uint2 v;
        v.x = pack2bf(a0, a1, term);
        v.y = pack2bf(b0, b1, term);
        g_wxf[j] = v;
    }
}

// smem: [0,12800) xn hi/lo -> D partials -> yhi plane (stride 392)
//       [12800,37632) u [16][388] f32 -> uc hi/lo planes (stride 388 bf16 each)
//       [37632,62464) z [16][388] f32 (y packed in place) -> ylo plane
//       [62464,65536) db [16][48]
__global__ __launch_bounds__(NTHR, 3)
void mamba_fused_kernel(const float* __restrict__ x,
                        const float* __restrict__ norm_w,
                        const float* __restrict__ conv_w,
                        const float* __restrict__ conv_b,
                        const float* __restrict__ dt_proj_w,
                        const float* __restrict__ dt_proj_b,
                        const float* __restrict__ A_log,
                        const float* __restrict__ Dp,
                        float* __restrict__ out)
{
    extern __shared__ char smraw[];
    __nv_bfloat16* s_xnh = (__nv_bfloat16*)(smraw);
    __nv_bfloat16* s_xnl = (__nv_bfloat16*)(smraw + 6400);
    __nv_bfloat16* s_yhi = (__nv_bfloat16*)(smraw);
    __nv_bfloat16* s_ylo = (__nv_bfloat16*)(smraw + 37632);
    __nv_bfloat16* s_uch = (__nv_bfloat16*)(smraw + 12800);
    __nv_bfloat16* s_ucl = s_uch + T_LEN * UCS;   // +12416 B
    float* s_part = (float*)(smraw);
    float* s_u  = (float*)(smraw + 12800);
    float* s_z  = (float*)(smraw + 37632);
    float* s_db = (float*)(smraw + 62464);

    const int tid  = threadIdx.x;
    const int lane = tid & 31;
    const int wid  = tid >> 5;
    const int g4   = lane >> 2;
    const int m2   = (lane & 3) * 2;

    const int n  = blockIdx.x;
    const int b  = n / HW;
    const int hw = n - b * HW;
    const size_t tstride = (size_t)HW * C_DIM;
    const size_t base0   = ((size_t)b * T_LEN * HW + hw) * C_DIM;

    // ---- A: load + RMSNorm -> xn hi/lo ----
    for (int t = wid; t < T_LEN; t += 12) {
        const float* row = x + base0 + (size_t)t * tstride;
        float v[6], ss = 0.f;
        #pragma unroll
        for (int i = 0; i < 6; i++) { v[i] = row[lane + 32 * i]; ss = fmaf(v[i], v[i], ss); }
        #pragma unroll
        for (int o = 16; o; o >>= 1) ss += __shfl_xor_sync(0xffffffffu, ss, o);
        float nrm = rsqrtf(ss * (1.0f / 192.0f) + 1e-6f);
        #pragma unroll
        for (int i = 0; i < 6; i++) {
            int c = lane + 32 * i;
            float xv = v[i] * nrm * norm_w[c];
            __nv_bfloat16 h = __float2bfloat16(xv);
            s_xnh[t * XNS + c] = h;
            s_xnl[t * XNS + c] = __float2bfloat16(xv - __bfloat162float(h));
        }
    }
    __syncthreads();

    // ---- B: in_proj via bf16 MMA (champion-identical) ----
    {
        float acc[32];
        #pragma unroll
        for (int i = 0; i < 32; i++) acc[i] = 0.f;
        #pragma unroll 1
        for (int ks = 0; ks < 12; ks++) {
            int kk = ks * 16 + m2;
            uint32_t ah0 = *(const uint32_t*)(s_xnh + g4 * XNS + kk);
            uint32_t ah1 = *(const uint32_t*)(s_xnh + (g4 + 8) * XNS + kk);
            uint32_t ah2 = *(const uint32_t*)(s_xnh + g4 * XNS + kk + 8);
            uint32_t ah3 = *(const uint32_t*)(s_xnh + (g4 + 8) * XNS + kk + 8);
            uint32_t al0 = *(const uint32_t*)(s_xnl + g4 * XNS + kk);
            uint32_t al1 = *(const uint32_t*)(s_xnl + (g4 + 8) * XNS + kk);
            uint32_t al2 = *(const uint32_t*)(s_xnl + g4 * XNS + kk + 8);
            uint32_t al3 = *(const uint32_t*)(s_xnl + (g4 + 8) * XNS + kk + 8);
            #pragma unroll
            for (int ng = 0; ng < 8; ng++) {
                int gng = wid * 8 + ng;
                uint2 bh = g_w1f[((ks * 96 + gng) * 2 + 0) * 32 + lane];
                uint2 bl = g_w1f[((ks * 96 + gng) * 2 + 1) * 32 + lane];
                MMA_BF16(acc + ng * 4, ah0, ah1, ah2, ah3, bh.x, bh.y);
                MMA_BF16(acc + ng * 4, al0, al1, al2, al3, bh.x, bh.y);
                MMA_BF16(acc + ng * 4, ah0, ah1, ah2, ah3, bl.x, bl.y);
            }
        }
        #pragma unroll
        for (int ng = 0; ng < 8; ng++) {
            int gc = wid * 64 + ng * 8 + m2;
            float d0 = acc[ng*4+0], d1 = acc[ng*4+1], d2 = acc[ng*4+2], d3 = acc[ng*4+3];
            if (gc < DIN) {
                *(float2*)(s_u + g4 * UST + gc)       = make_float2(d0, d1);
                *(float2*)(s_u + (g4 + 8) * UST + gc) = make_float2(d2, d3);
            } else {
                int zc = gc - DIN;
                *(float2*)(s_z + g4 * UST + zc)       = make_float2(siluf(d0), siluf(d1));
                *(float2*)(s_z + (g4 + 8) * UST + zc) = make_float2(siluf(d2), siluf(d3));
            }
        }
    }
    __syncthreads();

    // ---- C: conv + silu; stage u in regs, emit uc hi/lo planes over s_u ----
    {
        const int c = tid;
        float uv[T_LEN];
        #pragma unroll
        for (int t = 0; t < T_LEN; t++) uv[t] = s_u[t * UST + c];
        __syncthreads();   // all u reads staged before plane writes clobber s_u
        const float4 cw = *(const float4*)(conv_w + c * 4);
        const float cb = conv_b[c];
        float um3 = 0.f, um2 = 0.f, um1 = 0.f;
        #pragma unroll
        for (int t = 0; t < T_LEN; t++) {
            float u0 = uv[t];
            float a = cb;
            a = fmaf(um3, cw.x, a);
            a = fmaf(um2, cw.y, a);
            a = fmaf(um1, cw.z, a);
            a = fmaf(u0,  cw.w, a);
            float uc = siluf(a);
            __nv_bfloat16 h = __float2bfloat16(uc);
            s_uch[t * UCS + c] = h;
            s_ucl[t * UCS + c] = __float2bfloat16(uc - __bfloat162float(h));
            um3 = um2; um2 = um1; um1 = u0;
        }
    }
    __syncthreads();

    // ---- D: x_proj via bf16 MMA (6 n-groups x 2 k-halves across 12 warps) --
    {
        const int ng   = wid % 6;
        const int half = wid / 6;
        float acc[4] = {0.f, 0.f, 0.f, 0.f};
        #pragma unroll 1
        for (int ks = half * 12; ks < half * 12 + 12; ks++) {
            int kk = ks * 16 + m2;
            uint32_t ah0 = *(const uint32_t*)(s_uch + g4 * UCS + kk);
            uint32_t ah1 = *(const uint32_t*)(s_uch + (g4 + 8) * UCS + kk);
            uint32_t ah2 = *(const uint32_t*)(s_uch + g4 * UCS + kk + 8);
            uint32_t ah3 = *(const uint32_t*)(s_uch + (g4 + 8) * UCS + kk + 8);
            uint32_t al0 = *(const uint32_t*)(s_ucl + g4 * UCS + kk);
            uint32_t al1 = *(const uint32_t*)(s_ucl + (g4 + 8) * UCS + kk);
            uint32_t al2 = *(const uint32_t*)(s_ucl + g4 * UCS + kk + 8);
            uint32_t al3 = *(const uint32_t*)(s_ucl + (g4 + 8) * UCS + kk + 8);
            uint2 bh = g_wxf[((ks * 6 + ng) * 2 + 0) * 32 + lane];
            uint2 bl = g_wxf[((ks * 6 + ng) * 2 + 1) * 32 + lane];
            MMA_BF16(acc, ah0, ah1, ah2, ah3, bh.x, bh.y);
            MMA_BF16(acc, al0, al1, al2, al3, bh.x, bh.y);
            MMA_BF16(acc, ah0, ah1, ah2, ah3, bl.x, bl.y);
        }
        float* pp = s_part + half * 768;   // 16*48 floats per half
        *(float2*)(pp + g4 * DB_STR + ng * 8 + m2)       = make_float2(acc[0], acc[1]);
        *(float2*)(pp + (g4 + 8) * DB_STR + ng * 8 + m2) = make_float2(acc[2], acc[3]);
    }
    __syncthreads();
    {   // reduce 2 halves -> db (all 384 threads: 16 t x 24 float2 cols)
        int t = tid / 24, j2 = tid % 24;
        int o = t * DB_STR + 2 * j2;
        float2 p0 = *(const float2*)(s_part + o);
        float2 p1 = *(const float2*)(s_part + 768 + o);
        *(float2*)(s_db + o) = make_float2(p0.x + p1.x, p0.y + p1.y);
    }
    __syncthreads();

    // ---- E: dt_proj + softplus -> registers ----
    float dtv[T_LEN];
    {
        const int c = tid;
        float wreg[DTRANK];
        #pragma unroll
        for (int r = 0; r < DTRANK; r++) wreg[r] = dt_proj_w[r * DIN + c];
        const float bias = dt_proj_b[c];
        #pragma unroll
        for (int t = 0; t < T_LEN; t++) {
            const float4* dr = (const float4*)(s_db + t * DB_STR);
            float4 d0 = dr[0], d1 = dr[1], d2 = dr[2];
            float a = bias;
            a=fmaf(d0.x,wreg[0],a); a=fmaf(d0.y,wreg[1],a); a=fmaf(d0.z,wreg[2],a); a=fmaf(d0.w,wreg[3],a);
            a=fmaf(d1.x,wreg[4],a); a=fmaf(d1.y,wreg[5],a); a=fmaf(d1.z,wreg[6],a); a=fmaf(d1.w,wreg[7],a);
            a=fmaf(d2.x,wreg[8],a); a=fmaf(d2.y,wreg[9],a); a=fmaf(d2.z,wreg[10],a); a=fmaf(d2.w,wreg[11],a);
            dtv[t] = (a > 20.f) ? a : log1pf(__expf(a));
        }
    }

    // ---- F: selective scan; uc from planes; packed y over z in place ----
    {
        const int c = tid;
        float A[DSTATE];
        const float4* Ap = (const float4*)(A_log + c * DSTATE);
        #pragma unroll
        for (int q = 0; q < 4; q++) {
            float4 av = Ap[q];
            A[4*q+0] = -__expf(av.x); A[4*q+1] = -__expf(av.y);
            A[4*q+2] = -__expf(av.z); A[4*q+3] = -__expf(av.w);
        }
        float h[DSTATE];
        #pragma unroll
        for (int s = 0; s < DSTATE; s++) h[s] = 0.f;
        const float Dc = Dp[c];
        #pragma unroll 1
        for (int t = 0; t < T_LEN; t++) {
            float dt_t = dtv[t];
            float ucv  = __bfloat162float(s_uch[t * UCS + c])
                       + __bfloat162float(s_ucl[t * UCS + c]);
            float du   = dt_t * ucv;
            const float4* B4 = (const float4*)(s_db + t * DB_STR + DTRANK);
            const float4* C4 = (const float4*)(s_db + t * DB_STR + DTRANK + DSTATE);
            float y = 0.f;
            #pragma unroll
            for (int q = 0; q < 4; q++) {
                float4 Bv = B4[q], Cv = C4[q];
                float dA, hb;
                dA=__expf(dt_t*A[4*q+0]); hb=fmaf(h[4*q+0],dA,du*Bv.x); h[4*q+0]=hb; y=fmaf(hb,Cv.x,y);
                dA=__expf(dt_t*A[4*q+1]); hb=fmaf(h[4*q+1],dA,du*Bv.y); h[4*q+1]=hb; y=fmaf(hb,Cv.y,y);
                dA=__expf(dt_t*A[4*q+2]); hb=fmaf(h[4*q+2],dA,du*Bv.z); h[4*q+2]=hb; y=fmaf(hb,Cv.z,y);
                dA=__expf(dt_t*A[4*q+3]); hb=fmaf(h[4*q+3],dA,du*Bv.w); h[4*q+3]=hb; y=fmaf(hb,Cv.w,y);
            }
            y = fmaf(ucv, Dc, y);
            float yz = y * s_z[t * UST + c];
            *(uint32_t*)(s_z + t * UST + c) = bfpack(yz);
        }
    }

    // ---- repack packed y -> yhi plane + ylo plane ----
    {
        const int c = tid;
        uint32_t yv[T_LEN];
        #pragma unroll
        for (int t = 0; t < T_LEN; t++) yv[t] = *(const uint32_t*)(s_z + t * UST + c);
        __syncthreads();
        uint16_t* ph = (uint16_t*)s_yhi;
        uint16_t* pl = (uint16_t*)s_ylo;
        #pragma unroll
        for (int t = 0; t < T_LEN; t++) {
            ph[t * YST + c] = (uint16_t)(yv[t] & 0xffff);
            pl[t * YST + c] = (uint16_t)(yv[t] >> 16);
        }
    }
    __syncthreads();

    // ---- G: out_proj via bf16 MMA + residual (champion-identical) ----
    {
        float acc[8];
        #pragma unroll
        for (int i = 0; i < 8; i++) acc[i] = 0.f;
        #pragma unroll 1
        for (int ks = 0; ks < 24; ks++) {
            int kk = ks * 16 + m2;
            uint2 bh0 = g_w2f[((ks * 24 + wid * 2 + 0) * 2 + 0) * 32 + lane];
            uint2 bl0 = g_w2f[((ks * 24 + wid * 2 + 0) * 2 + 1) * 32 + lane];
            uint2 bh1 = g_w2f[((ks * 24 + wid * 2 + 1) * 2 + 0) * 32 + lane];
            uint2 bl1 = g_w2f[((ks * 24 + wid * 2 + 1) * 2 + 1) * 32 + lane];
            uint32_t ah0 = *(const uint32_t*)(s_yhi + g4 * YST + kk);
            uint32_t ah1 = *(const uint32_t*)(s_yhi + (g4 + 8) * YST + kk);
            uint32_t ah2 = *(const uint32_t*)(s_yhi + g4 * YST + kk + 8);
            uint32_t ah3 = *(const uint32_t*)(s_yhi + (g4 + 8) * YST + kk + 8);
            uint32_t al0 = *(const uint32_t*)(s_ylo + g4 * YST + kk);
            uint32_t al1 = *(const uint32_t*)(s_ylo + (g4 + 8) * YST + kk);
            uint32_t al2 = *(const uint32_t*)(s_ylo + g4 * YST + kk + 8);
            uint32_t al3 = *(const uint32_t*)(s_ylo + (g4 + 8) * YST + kk + 8);
            MMA_BF16(acc + 0, ah0, ah1, ah2, ah3, bh0.x, bh0.y);
            MMA_BF16(acc + 0, al0, al1, al2, al3, bh0.x, bh0.y);
            MMA_BF16(acc + 0, ah0, ah1, ah2, ah3, bl0.x, bl0.y);
            MMA_BF16(acc + 4, ah0, ah1, ah2, ah3, bh1.x, bh1.y);
            MMA_BF16(acc + 4, al0, al1, al2, al3, bh1.x, bh1.y);
            MMA_BF16(acc + 4, ah0, ah1, ah2, ah3, bl1.x, bl1.y);
        }
        #pragma unroll
        for (int ng = 0; ng < 2; ng++) {
            int gc = (wid * 2 + ng) * 8 + m2;
            size_t ga = base0 + (size_t)g4 * tstride + gc;
            size_t gb = base0 + (size_t)(g4 + 8) * tstride + gc;
            float2 xa = *(const float2*)(x + ga);
            float2 xb = *(const float2*)(x + gb);
            *(float2*)(out + ga) = make_float2(xa.x + acc[ng*4+0], xa.y + acc[ng*4+1]);
            *(float2*)(out + gb) = make_float2(xb.x + acc[ng*4+2], xb.y + acc[ng*4+3]);
        }
    }
}

extern "C" void kernel_launch(void* const* d_in, const int* in_sizes, int n_in,
                              void* d_out, int out_size)
{
    (void)in_sizes; (void)n_in; (void)out_size;
    const float* x         = (const float*)d_in[0];
    const float* norm_w    = (const float*)d_in[1];
    const float* in_proj_w = (const float*)d_in[2];
    const float* conv_w    = (const float*)d_in[3];
    const float* conv_b    = (const float*)d_in[4];
    const float* x_proj_w  = (const float*)d_in[5];
    const float* dt_proj_w = (const float*)d_in[6];
    const float* dt_proj_b = (const float*)d_in[7];
    const float* A_log     = (const float*)d_in[8];
    const float* Dp        = (const float*)d_in[9];
    const float* out_pw    = (const float*)d_in[10];
    float* out = (float*)d_out;

    prep_kernel<<<468, 256>>>(in_proj_w, out_pw, x_proj_w);   // 119808 threads

    const int smem_bytes = 65536;
    cudaFuncSetAttribute(mamba_fused_kernel,
                         cudaFuncAttributeMaxDynamicSharedMemorySize, smem_bytes);
    mamba_fused_kernel<<<2 * HW, NTHR, smem_bytes>>>(
        x, norm_w, conv_w, conv_b,
        dt_proj_w, dt_proj_b, A_log, Dp, out);
}